// round 7
// baseline (speedup 1.0000x reference)
#include <cuda_runtime.h>
#include <cstdint>

#define T 512
#define C 6
#define R 256
#define BPC 4           // batches per 2-CTA cluster
#define NBLK 128        // 64 clusters x 2 CTAs = 128 CTAs, one wave

typedef unsigned long long ull;

__device__ __forceinline__ void fma2(ull& d, ull a, ull b) {
    asm("fma.rn.f32x2 %0, %1, %2, %0;" : "+l"(d) : "l"(a), "l"(b));
}
__device__ __forceinline__ float sum2(ull a) {
    float lo, hi;
    asm("mov.b64 {%0,%1}, %2;" : "=f"(lo), "=f"(hi) : "l"(a));
    return lo + hi;
}
__device__ __forceinline__ ull pack2(float lo, float hi) {
    ull u; asm("mov.b64 %0, {%1,%2};" : "=l"(u) : "f"(lo), "f"(hi));
    return u;
}
// tanh(z) = 1 - 2/(exp(2z)+1): exp->inf gives exactly 1 (no NaN); abs err ~1e-7.
__device__ __forceinline__ float tanh_fast(float z) {
    float e = __expf(2.0f * z);
    return 1.0f - __fdividef(2.0f, e + 1.0f);
}
__device__ __forceinline__ uint32_t smem_u32(const void* p) {
    return (uint32_t)__cvta_generic_to_shared(p);
}
__device__ __forceinline__ uint32_t mapa_u32(uint32_t laddr, uint32_t peer) {
    uint32_t r;
    asm("mapa.shared::cluster.u32 %0, %1, %2;" : "=r"(r) : "r"(laddr), "r"(peer));
    return r;
}

// Cluster-2 split-K design:
//   Cluster = {CTA0: k,r in [0,128) ; CTA1: k,r in [128,256)}, 4 shared batches.
//   ALL of this CTA's W-half (128k x 256r = 128KB) lives in registers:
//     warp w owns k_local [16w,16w+16); lane l owns r = 64g+2l+s (8 r's)
//     -> wreg[64] ull, NO W smem traffic at all.
//   Per step: phase1 partials -> local red; bar; stage2 reduces 8 warps,
//   sends reduced PEER-half (2KB) via st.async+mbarrier tx into peer inbox,
//   finalizes OWN half (own r-half == own k-half, so h never crosses CTAs).
//   Sync: producer-elected remote expect_tx (step start) + consumer
//   acquire-cluster parity wait; 2-deep inbox ping-pong; skew provably < 2.
struct __align__(16) Smem {
    float red[8][4][256];     // 32 KB  phase1 partials [warp][batch][r_global]
    float inb[2][2][128][2];  // 4 KB   inbox [buf][bs][rhat][b-pair]
    float hsm[4][128];        // 2 KB   this CTA's h half [batch][r_local]
    ull   bar[2];             // inbox mbarriers (ping-pong)
};

__global__ void __launch_bounds__(256, 1) __cluster_dims__(2, 1, 1)
esn_kernel(const float* __restrict__ x, const float* __restrict__ W_in,
           const float* __restrict__ W_res, float* __restrict__ out)
{
    __shared__ Smem sm;
    const int tid = threadIdx.x;
    const int w = tid >> 5, l = tid & 31;
    uint32_t rank;
    asm("mov.u32 %0, %%cluster_ctarank;" : "=r"(rank));
    const uint32_t peer = rank ^ 1u;
    const int b0 = (int)(blockIdx.x >> 1) * BPC;

    if (tid == 0) {
        asm volatile("mbarrier.init.shared.b64 [%0], 1;"
                     :: "r"(smem_u32(&sm.bar[0])) : "memory");
        asm volatile("mbarrier.init.shared.b64 [%0], 1;"
                     :: "r"(smem_u32(&sm.bar[1])) : "memory");
    }
    ((float*)sm.hsm)[tid]       = 0.0f;   // h(-1) = 0
    ((float*)sm.hsm)[tid + 256] = 0.0f;

    // W-half in registers: wreg[p*8+gs] = (W[k0][r], W[k0+1][r]),
    // k0 = rank*128 + 16w + 2p, r = 64*(gs>>1) + 2l + (gs&1).
    ull wreg[64];
    {
        const int kg = (int)rank * 128 + 16 * w;
        #pragma unroll
        for (int p = 0; p < 8; ++p) {
            const int k0 = kg + 2 * p;
            #pragma unroll
            for (int gs = 0; gs < 8; ++gs) {
                const int r = 64 * (gs >> 1) + 2 * l + (gs & 1);
                wreg[p * 8 + gs] = pack2(W_res[k0 * R + r], W_res[(k0 + 1) * R + r]);
            }
        }
    }

    const int rhat  = tid & 127;                 // stage2 row within own half
    const int bs    = tid >> 7;                  // stage2 batches {bs, bs+2}
    const int rown  = (int)rank * 128 + rhat;    // global r this thread finalizes
    const int rpeerg = (int)peer * 128 + rhat;   // global r it reduces-and-sends

    float win[C];
    #pragma unroll
    for (int c = 0; c < C; ++c) win[c] = W_in[c * R + rown];

    __syncthreads();   // mbar init + hsm zeros visible CTA-locally
    asm volatile("barrier.cluster.arrive.aligned;" ::: "memory");
    asm volatile("barrier.cluster.wait.aligned;"  ::: "memory");

    uint32_t rbar[2], rin;
    rbar[0] = mapa_u32(smem_u32(&sm.bar[0]), peer);
    rbar[1] = mapa_u32(smem_u32(&sm.bar[1]), peer);
    rin     = mapa_u32(smem_u32(&sm.inb[0][0][0][0]), peer)
            + (uint32_t)((bs * 128 + rhat) * 8);

    const float2* xA = (const float2*)(x + (size_t)(b0 + bs) * T * C);
    const float2* xB = (const float2*)(x + (size_t)(b0 + bs + 2) * T * C);
    float* oA = out + (size_t)(b0 + bs) * T * R + rown;
    float* oB = out + (size_t)(b0 + bs + 2) * T * R + rown;

    const int kb = 16 * w;

    for (int t = 0; t < T; ++t) {
        const int j = t & 1;
        // Producer-side expectation on the PEER's inbox barrier for this step.
        // Issued before any st.async of this step (program order, tid 0), and
        // tx-count may legally go negative if another thread's st.async races it.
        if (tid == 0) {
            asm volatile(
                "mbarrier.arrive.expect_tx.release.cluster.shared::cluster.b64 _, [%0], %1;"
                :: "r"(rbar[j]), "r"(2048) : "memory");
        }
        // x prefetch (consumed ~1000 cycles later)
        float2 xa = xA[3 * t], xb = xA[3 * t + 1], xc = xA[3 * t + 2];
        float2 xd = xB[3 * t], xe = xB[3 * t + 1], xf = xB[3 * t + 2];

        // ---- phase1: partials over own k-half, two batch-pairs to cap regs ----
        #pragma unroll
        for (int half = 0; half < 2; ++half) {
            const int b = 2 * half;
            ulonglong2 hA[4], hB[4];
            const ulonglong2* pa = (const ulonglong2*)&sm.hsm[b][kb];     // broadcast
            const ulonglong2* pb = (const ulonglong2*)&sm.hsm[b + 1][kb]; // broadcast
            #pragma unroll
            for (int i = 0; i < 4; ++i) { hA[i] = pa[i]; hB[i] = pb[i]; }

            ull acc[16];
            #pragma unroll
            for (int i = 0; i < 16; ++i) acc[i] = 0;
            #pragma unroll
            for (int p = 0; p < 8; ++p) {
                const ull h0 = (p & 1) ? hA[p >> 1].y : hA[p >> 1].x;
                const ull h1 = (p & 1) ? hB[p >> 1].y : hB[p >> 1].x;
                #pragma unroll
                for (int gs = 0; gs < 8; ++gs) {
                    fma2(acc[gs * 2 + 0], h0, wreg[p * 8 + gs]);
                    fma2(acc[gs * 2 + 1], h1, wreg[p * 8 + gs]);
                }
            }
            #pragma unroll
            for (int g = 0; g < 4; ++g) {   // conflict-free 8B-stride STS.64
                float2 v0 = make_float2(sum2(acc[(2 * g) * 2 + 0]),
                                        sum2(acc[(2 * g + 1) * 2 + 0]));
                float2 v1 = make_float2(sum2(acc[(2 * g) * 2 + 1]),
                                        sum2(acc[(2 * g + 1) * 2 + 1]));
                *(float2*)&sm.red[w][b][64 * g + 2 * l]     = v0;
                *(float2*)&sm.red[w][b + 1][64 * g + 2 * l] = v1;
            }
        }
        __syncthreads();   // bar#1: partials STS -> stage2 LDS

        // ---- stage2: 8-warp reduce; ship peer half; finish own half ----
        float so0 = 0.f, so1 = 0.f, sp0 = 0.f, sp1 = 0.f;
        #pragma unroll
        for (int ww = 0; ww < 8; ++ww) {   // stride-4B lanes: conflict-free
            so0 += sm.red[ww][bs][rown];      so1 += sm.red[ww][bs + 2][rown];
            sp0 += sm.red[ww][bs][rpeerg];    sp1 += sm.red[ww][bs + 2][rpeerg];
        }
        {
            ull sv = pack2(sp0, sp1);
            asm volatile(
                "st.async.shared::cluster.mbarrier::complete_tx::bytes.b64 [%0], %1, [%2];"
                :: "r"(rin + (uint32_t)j * 2048u), "l"(sv), "r"(rbar[j]) : "memory");
        }
        float xq0 = xa.x * win[0] + xa.y * win[1] + xb.x * win[2]
                  + xb.y * win[3] + xc.x * win[4] + xc.y * win[5];
        float xq1 = xd.x * win[0] + xd.y * win[1] + xe.x * win[2]
                  + xe.y * win[3] + xf.x * win[4] + xf.y * win[5];

        // wait for peer's reduced partials (acquire at cluster scope)
        {
            const uint32_t mb  = smem_u32(&sm.bar[j]);
            const uint32_t par = (uint32_t)(t >> 1) & 1u;
            uint32_t done;
            asm volatile(
                "{\n\t.reg .pred p;\n\t"
                "mbarrier.try_wait.parity.acquire.cluster.shared::cta.b64 p, [%1], %2;\n\t"
                "selp.b32 %0, 1, 0, p;\n\t}"
                : "=r"(done) : "r"(mb), "r"(par) : "memory");
            if (!done) {
                asm volatile(
                    "{\n\t.reg .pred P1;\n\t"
                    "W0_%=:\n\t"
                    "mbarrier.try_wait.parity.acquire.cluster.shared::cta.b64 P1, [%0], %1;\n\t"
                    "@P1 bra.uni W1_%=;\n\t"
                    "bra.uni W0_%=;\n\t"
                    "W1_%=:\n\t}"
                    :: "r"(mb), "r"(par) : "memory");
            }
        }
        float2 pin = *(const float2*)&sm.inb[j][bs][rhat][0];
        float h0 = tanh_fast(so0 + pin.x + xq0);
        float h1 = tanh_fast(so1 + pin.y + xq1);
        sm.hsm[bs][rhat]     = h0;          // own half: next step's k-range
        sm.hsm[bs + 2][rhat] = h1;
        oA[(size_t)t * R] = h0;             // coalesced STG
        oB[(size_t)t * R] = h1;

        __syncthreads();   // bar#2: hsm writes -> next phase1 reads;
                           //         stage2 red reads -> next phase1 STS
    }
}

extern "C" void kernel_launch(void* const* d_in, const int* in_sizes, int n_in,
                              void* d_out, int out_size) {
    const float* x     = (const float*)d_in[0];
    const float* W_in  = (const float*)d_in[1];
    const float* W_res = (const float*)d_in[2];
    float* out = (float*)d_out;
    esn_kernel<<<NBLK, 256>>>(x, W_in, W_res, out);
}

// round 8
// speedup vs baseline: 1.1029x; 1.1029x over previous
#include <cuda_runtime.h>
#include <cstdint>

#define T 512
#define C 6
#define R 256
#define BC 2
#define NBLK 128           // 128 CTAs x 2 batches, one wave
#define NTHR 512           // 16 warps, 4 per SMSP

// shared layout (floats): Wsm 32768 | red 4096 | hsm 512 | xsm 6144
#define WSM_F 32768
#define RED_F 4096
#define HSM_F 512
#define XSM_F 6144
#define SMEM_BYTES ((WSM_F + RED_F + HSM_F + XSM_F) * 4)   // 174080

typedef unsigned long long ull;

__device__ __forceinline__ void fma2(ull& d, ull a, ull b) {
    asm("fma.rn.f32x2 %0, %1, %2, %0;" : "+l"(d) : "l"(a), "l"(b));
}
__device__ __forceinline__ float sum2(ull a) {
    float lo, hi;
    asm("mov.b64 {%0,%1}, %2;" : "=f"(lo), "=f"(hi) : "l"(a));
    return lo + hi;
}
__device__ __forceinline__ ull pack2(float lo, float hi) {
    ull u; asm("mov.b64 %0, {%1,%2};" : "=l"(u) : "f"(lo), "f"(hi));
    return u;
}
// tanh(z) = 1 - 2/(exp(2z)+1): exp->inf gives exactly 1 (no NaN); abs err ~1e-7.
__device__ __forceinline__ float tanh_fast(float z) {
    float e = __expf(2.0f * z);
    return 1.0f - __fdividef(2.0f, e + 1.0f);
}

// 16-warp split:
//   warp w = 2i+p: k-slice i in [0,8) -> k in [32i,32i+32); r-half p.
//     k rows [32i, 32i+16)      -> registers (wreg: 8 k-pairs x 4 r = 32 ull)
//     k rows [32i+16, 32i+32)   -> smem Wsm (read once per step, conflict-free)
//   lane l owns r = 128p + 32g + l, g = 0..3 (4 outputs x 2 batches).
//   red[i][b][r]: 8 partials per (r,b) -> phase2 thread (b = tid>>8, r = tid&255)
//   reduces 8, adds x-projection, tanh, stores h + out.
__global__ void __launch_bounds__(NTHR, 1)
esn_kernel(const float* __restrict__ x, const float* __restrict__ W_in,
           const float* __restrict__ W_res, float* __restrict__ out)
{
    extern __shared__ float sm[];
    float* Wsm = sm;                       // [i(8)][kg(4)][r(256)][j(4)]
    float* red = Wsm + WSM_F;              // [i(8)][b(2)][r(256)]
    float* hsm = red + RED_F;              // [b(2)][r(256)]
    float* xsm = hsm + HSM_F;              // [b(2)][t(512)][c(6)]

    const int tid = threadIdx.x;
    const int w = tid >> 5, l = tid & 31;
    const int i = w >> 1, p = w & 1;
    const int b0 = blockIdx.x * BC;

    // Stage x for both batches: 24KB contiguous, float4-coalesced.
    {
        const float4* xg = (const float4*)(x + (size_t)b0 * T * C);
        float4* xs4 = (float4*)xsm;
        #pragma unroll
        for (int m = tid; m < (BC * T * C) / 4; m += NTHR) xs4[m] = xg[m];
    }
    // Stage smem W half: rows k = 32*(kk>>4) + 16 + (kk&15), kk = 0..127,
    // packed so one float4 = 4 consecutive k for one r.
    for (int m = tid; m < WSM_F; m += NTHR) {
        int r = m & 255, kk = m >> 8;
        int ii = kk >> 4, rem = kk & 15, kg = rem >> 2, j = rem & 3;
        Wsm[(((ii << 2) + kg) * 256 + r) * 4 + j] = W_res[(32 * ii + 16 + rem) * R + r];
    }
    // Register W half: k-pairs jp=0..7 -> k0 = 32i + 2jp, r = 128p + 32g + l.
    ull wreg[32];
    {
        const int kb = 32 * i;
        #pragma unroll
        for (int jp = 0; jp < 8; ++jp) {
            const int k0 = kb + 2 * jp;
            #pragma unroll
            for (int g = 0; g < 4; ++g) {
                const int r = 128 * p + 32 * g + l;
                wreg[jp * 4 + g] = pack2(W_res[k0 * R + r], W_res[(k0 + 1) * R + r]);
            }
        }
    }

    const int rme = tid & 255, bme = tid >> 8;     // phase2 identity
    float win[C];
    #pragma unroll
    for (int c = 0; c < C; ++c) win[c] = W_in[c * R + rme];

    hsm[tid] = 0.0f;                               // 512 floats, 512 threads
    __syncthreads();

    // Warp-uniform pointers
    const ulonglong2* hR0 = (const ulonglong2*)(hsm + 32 * i);          // b0, reg half
    const ulonglong2* hR1 = (const ulonglong2*)(hsm + 256 + 32 * i);    // b1, reg half
    const ulonglong2* hS0 = (const ulonglong2*)(hsm + 32 * i + 16);     // b0, smem half
    const ulonglong2* hS1 = (const ulonglong2*)(hsm + 256 + 32 * i + 16);
    const float4* Wp = (const float4*)Wsm + (i * 4) * 256 + 128 * p + l;
    float* red0 = red + (i * 2 + 0) * 256 + 128 * p + l;
    float* red1 = red + (i * 2 + 1) * 256 + 128 * p + l;
    const float2* xv = (const float2*)(xsm + (size_t)bme * T * C);
    float* o = out + (size_t)(b0 + bme) * T * R + rme;

    for (int t = 0; t < T; ++t) {
        // acc[g*2+b]: f32x2 lanes hold even/odd-k partials for r(g), batch b.
        ull acc[8];
        #pragma unroll
        for (int q = 0; q < 8; ++q) acc[q] = 0;

        // ---- register half: 8 k-pairs, h via 2 broadcast LDS.128 per batch/chunk
        #pragma unroll
        for (int q = 0; q < 4; ++q) {              // q: ulonglong2 = k-pairs 2q,2q+1
            ulonglong2 h0 = hR0[q];
            ulonglong2 h1 = hR1[q];
            #pragma unroll
            for (int g = 0; g < 4; ++g) {
                fma2(acc[g * 2 + 0], h0.x, wreg[(2 * q) * 4 + g]);
                fma2(acc[g * 2 + 1], h1.x, wreg[(2 * q) * 4 + g]);
                fma2(acc[g * 2 + 0], h0.y, wreg[(2 * q + 1) * 4 + g]);
                fma2(acc[g * 2 + 1], h1.y, wreg[(2 * q + 1) * 4 + g]);
            }
        }
        // ---- smem half: 4 k-groups of 4; W via conflict-free LDS.128
        #pragma unroll
        for (int kg = 0; kg < 4; ++kg) {
            ulonglong2 h0 = hS0[kg];               // pairs (2kg, 2kg+1), batch0
            ulonglong2 h1 = hS1[kg];               // batch1
            #pragma unroll
            for (int g = 0; g < 4; ++g) {
                float4 wv = Wp[kg * 256 + 32 * g]; // k group 4 for r(g)
                ull wlo = pack2(wv.x, wv.y);       // pair 2kg
                ull whi = pack2(wv.z, wv.w);       // pair 2kg+1
                fma2(acc[g * 2 + 0], h0.x, wlo);
                fma2(acc[g * 2 + 1], h1.x, wlo);
                fma2(acc[g * 2 + 0], h0.y, whi);
                fma2(acc[g * 2 + 1], h1.y, whi);
            }
        }

        // Publish partials (stride-4B STS.32, conflict-free).
        #pragma unroll
        for (int g = 0; g < 4; ++g) {
            red0[32 * g] = sum2(acc[g * 2 + 0]);
            red1[32 * g] = sum2(acc[g * 2 + 1]);
        }
        __syncthreads();   // partials STS -> phase2 LDS

        // ---- phase2: thread (bme, rme) reduces 8 partials + x-proj + tanh
        float s = 0.0f;
        #pragma unroll
        for (int q = 0; q < 8; ++q)
            s += red[(q * 2 + bme) * 256 + rme];

        float2 xa = xv[3 * t], xb = xv[3 * t + 1], xc = xv[3 * t + 2];
        float xp = xa.x * win[0] + xa.y * win[1] + xb.x * win[2]
                 + xb.y * win[3] + xc.x * win[4] + xc.y * win[5];

        float h = tanh_fast(s + xp);
        hsm[bme * 256 + rme] = h;
        o[(size_t)t * R] = h;                      // coalesced STG.32

        __syncthreads();   // hsm/red ready for next phase1
    }
}

extern "C" void kernel_launch(void* const* d_in, const int* in_sizes, int n_in,
                              void* d_out, int out_size) {
    const float* x     = (const float*)d_in[0];
    const float* W_in  = (const float*)d_in[1];
    const float* W_res = (const float*)d_in[2];
    float* out = (float*)d_out;

    cudaFuncSetAttribute(esn_kernel, cudaFuncAttributeMaxDynamicSharedMemorySize,
                         SMEM_BYTES);
    esn_kernel<<<NBLK, NTHR, SMEM_BYTES>>>(x, W_in, W_res, out);
}